// round 13
// baseline (speedup 1.0000x reference)
#include <cuda_runtime.h>
#include <cuda_fp16.h>
#include <cstdint>
#include <cstddef>

#define NROWS 65536
#define PLANE ((size_t)NROWS * 256)

__device__ __align__(128) __half g_xh [6 * PLANE];
__device__ __align__(128) __half g_q0h[3 * PLANE];
__device__ __align__(128) __half g_qa [3 * PLANE];
__device__ __align__(128) __half g_qb [3 * PLANE];
__device__ __align__(128) __half g_wcat[3 * 256 * 768];

#define SWZ(x) ((x) ^ (((x) >> 3) & 0x70))

// SMEM: bias 1KB, 3 stages of (A 16KB + B 16KB)
#define OFF_BIAS 0
#define OFF_STG  1024
#define STG_SZ   32768
#define SMEM_TOTAL (1024 + 3 * STG_SZ)   // 99328

__device__ __forceinline__ uint32_t s2u(const void* p) {
    return (uint32_t)__cvta_generic_to_shared(p);
}

#define CPA(dst, src) \
    asm volatile("cp.async.cg.shared.global [%0], [%1], 16;" \
                 :: "r"(dst), "l"(src) : "memory")
#define CPC() asm volatile("cp.async.commit_group;" ::: "memory")
#define CPW1() asm volatile("cp.async.wait_group 1;" ::: "memory")

#define LDSM4(r, addr) \
    asm volatile("ldmatrix.sync.aligned.m8n8.x4.shared.b16 {%0,%1,%2,%3}, [%4];" \
                 : "=r"((r)[0]), "=r"((r)[1]), "=r"((r)[2]), "=r"((r)[3]) \
                 : "r"(addr))

#define MMA(cr, av, b0v, b1v) \
    asm volatile("mma.sync.aligned.m16n8k16.row.col.f32.f16.f16.f32 " \
                 "{%0,%1,%2,%3}, {%4,%5,%6,%7}, {%8,%9}, {%0,%1,%2,%3};" \
                 : "+f"((cr)[0]), "+f"((cr)[1]), "+f"((cr)[2]), "+f"((cr)[3]) \
                 : "r"((av)[0]), "r"((av)[1]), "r"((av)[2]), "r"((av)[3]), \
                   "r"(b0v), "r"(b1v))

// ---------------- prep kernels ---------------------------------------------
__global__ void prep_xq_kernel(const float* __restrict__ x,
                               const float* __restrict__ q) {
    size_t t = (size_t)blockIdx.x * 256 + threadIdx.x;   // over PLANE/2
    size_t i2 = 2 * t;
    const float4* px = reinterpret_cast<const float4*>(x + i2 * 6);
    float4 r0 = px[0], r1 = px[1], r2 = px[2];
    __half2* xh2 = reinterpret_cast<__half2*>(g_xh);
    xh2[0 * (PLANE / 2) + t] = __floats2half2_rn(r0.x, r1.z);
    xh2[1 * (PLANE / 2) + t] = __floats2half2_rn(r0.y, r1.w);
    xh2[2 * (PLANE / 2) + t] = __floats2half2_rn(r0.z, r2.x);
    xh2[3 * (PLANE / 2) + t] = __floats2half2_rn(r0.w, r2.y);
    xh2[4 * (PLANE / 2) + t] = __floats2half2_rn(r1.x, r2.z);
    xh2[5 * (PLANE / 2) + t] = __floats2half2_rn(r1.y, r2.w);

    const float2* pq = reinterpret_cast<const float2*>(q + i2 * 3);
    float2 s0 = pq[0], s1 = pq[1], s2 = pq[2];
    __half2* qh2 = reinterpret_cast<__half2*>(g_q0h);
    qh2[0 * (PLANE / 2) + t] = __floats2half2_rn(s0.x, s1.y);
    qh2[1 * (PLANE / 2) + t] = __floats2half2_rn(s0.y, s2.x);
    qh2[2 * (PLANE / 2) + t] = __floats2half2_rn(s1.x, s2.y);
}
__global__ void prep_w_kernel(const float* __restrict__ W1,
                              const float* __restrict__ W2,
                              const float* __restrict__ W3) {
    uint32_t t = blockIdx.x * 256 + threadIdx.x;   // 3*256*768
    int l = t / 196608, r = t % 196608;
    int o = r / 768, k = r % 768;
    int j = k >> 8, c = k & 255;
    const float* W = (l == 0) ? W1 : (l == 1 ? W2 : W3);
    g_wcat[t] = __float2half(W[(o * 256 + c) * 3 + j]);
}

// ---------------- layer kernel ---------------------------------------------
// grid: (2 n-halves, 512 row-tiles, 3 groups), 256 threads
__global__ void __launch_bounds__(256, 2)
layer_kernel(int qin_sel, int qout_sel, const float* __restrict__ bias, int layer) {
    extern __shared__ char smem[];
    const int tid   = threadIdx.x;
    const int lane  = tid & 31;
    const int wid   = tid >> 5;
    const int warpM = wid & 3;       // 4 warps in M (32 rows each)
    const int warpN = wid >> 2;      // 2 warps in N (64 cols each)
    const int half  = blockIdx.x;
    const int row0  = blockIdx.y * 128;
    const int g     = blockIdx.z;
    const int ncta  = half * 128;

    const __half* __restrict__ qin =
        (qin_sel == 0) ? g_q0h : (qin_sel == 1 ? g_qa : g_qb);
    __half* __restrict__ qout = (qout_sel == 1) ? g_qa : g_qb;
    const __half* __restrict__ wc = g_wcat + (size_t)layer * (256 * 768);

    const __half* aplane[3];
    aplane[0] = g_xh + (size_t)(2 * g + 0) * PLANE + (size_t)row0 * 256;
    aplane[1] = g_xh + (size_t)(2 * g + 1) * PLANE + (size_t)row0 * 256;
    aplane[2] = qin  + (size_t)g * PLANE          + (size_t)row0 * 256;
    const __half* bsrc = wc + (size_t)ncta * 768;

    float* bias_s = reinterpret_cast<float*>(smem + OFF_BIAS);
    if (tid < 128) bias_s[tid] = bias[ncta + tid];

    const uint32_t sb = s2u(smem);
    const int ldm = tid >> 3, ldt = (tid & 7) * 8;

    // stg is a compile-time constant at every call site after unrolling
    auto loadChunk = [&](int c, int stg) {
        const __half* sA = aplane[c >> 2] + (c & 3) * 64;
        const uint32_t dA = sb + OFF_STG + stg * STG_SZ;
        #pragma unroll
        for (int it = 0; it < 4; ++it) {           // A: 128 rows x 128B
            int m = ldm + it * 32;
            CPA(dA + SWZ(m * 128 + ldt * 2), sA + (size_t)m * 256 + ldt);
        }
        const __half* sB = bsrc + c * 64;
        const uint32_t dB = dA + 16384;
        #pragma unroll
        for (int it = 0; it < 4; ++it) {           // B: 128 n-rows x 128B
            int n = ldm + it * 32;
            CPA(dB + SWZ(n * 128 + ldt * 2), sB + (size_t)n * 768 + ldt);
        }
    };

    float c[2][8][4];
    #pragma unroll
    for (int mt = 0; mt < 2; ++mt)
        #pragma unroll
        for (int j = 0; j < 8; ++j)
            #pragma unroll
            for (int e = 0; e < 4; ++e) c[mt][j][e] = 0.0f;

    const int arow = warpM * 32 + (lane & 15);
    const int akb  = (lane >> 4) * 8;
    const int brow = warpN * 64 + ((lane >> 3) & 2) * 4 + (lane & 7);
    const int bkb  = ((lane >> 3) & 1) * 8;

    uint32_t a[2][2][4], b[2][4][4];

    // per-chunk body; s (stage) is compile-time constant at each call site
    auto chunkBody = [&](int i, int s, bool doLoad) {
        CPW1();
        __syncthreads();
        if (doLoad) loadChunk(i + 2, (s + 2) % 3);
        CPC();

        const uint32_t aoff = sb + OFF_STG + s * STG_SZ;
        const uint32_t boff = aoff + 16384;

        // prime ks=0 frags
        #pragma unroll
        for (int mt = 0; mt < 2; ++mt)
            LDSM4(a[0][mt], aoff + SWZ((arow + mt * 16) * 128 + akb * 2));
        #pragma unroll
        for (int j = 0; j < 4; ++j)
            LDSM4(b[0][j], boff + SWZ((brow + j * 16) * 128 + bkb * 2));

        #pragma unroll
        for (int ks = 0; ks < 4; ++ks) {
            const int cur = ks & 1, nxt = cur ^ 1;
            if (ks < 3) {
                const int k0 = (ks + 1) * 16;
                #pragma unroll
                for (int mt = 0; mt < 2; ++mt)
                    LDSM4(a[nxt][mt], aoff + SWZ((arow + mt * 16) * 128 + (k0 + akb) * 2));
                #pragma unroll
                for (int j = 0; j < 4; ++j)
                    LDSM4(b[nxt][j], boff + SWZ((brow + j * 16) * 128 + (k0 + bkb) * 2));
            }
            #pragma unroll
            for (int mt = 0; mt < 2; ++mt)
                #pragma unroll
                for (int j = 0; j < 4; ++j) {
                    MMA(c[mt][2 * j],     a[cur][mt], b[cur][j][0], b[cur][j][1]);
                    MMA(c[mt][2 * j + 1], a[cur][mt], b[cur][j][2], b[cur][j][3]);
                }
        }
    };

    loadChunk(0, 0); CPC();
    loadChunk(1, 1); CPC();

    #pragma unroll 1
    for (int it = 0; it < 4; ++it) {
        const int i0 = it * 3;
        chunkBody(i0 + 0, 0, true);          // loads chunk i0+2  (<=11 always)
        chunkBody(i0 + 1, 1, it < 3);        // loads chunk i0+3
        chunkBody(i0 + 2, 2, it < 3);        // loads chunk i0+4
    }

    // epilogue: bias + relu -> fp16 planar (final layer relu lives in finalize)
    __half* plane = qout + (size_t)g * PLANE;
    const int do_relu = (layer != 2);
    #pragma unroll
    for (int mt = 0; mt < 2; ++mt) {
        const int r0 = row0 + warpM * 32 + mt * 16 + (lane >> 2);
        #pragma unroll
        for (int j = 0; j < 8; ++j) {
            const int cl = warpN * 64 + j * 8 + (lane & 3) * 2;
            const float b0 = bias_s[cl], b1 = bias_s[cl + 1];
            float v0 = c[mt][j][0] + b0, v1 = c[mt][j][1] + b1;
            float v2 = c[mt][j][2] + b0, v3 = c[mt][j][3] + b1;
            if (do_relu) {
                v0 = fmaxf(v0, 0.0f); v1 = fmaxf(v1, 0.0f);
                v2 = fmaxf(v2, 0.0f); v3 = fmaxf(v3, 0.0f);
            }
            const int gc = ncta + cl;
            *reinterpret_cast<__half2*>(plane + (size_t)r0 * 256 + gc) =
                __floats2half2_rn(v0, v1);
            *reinterpret_cast<__half2*>(plane + (size_t)(r0 + 8) * 256 + gc) =
                __floats2half2_rn(v2, v3);
        }
    }
}

// ---------------- finalize: residual(fp16) + relu + interleave -------------
__global__ void finalize_kernel(float* __restrict__ out) {
    size_t t = (size_t)blockIdx.x * 256 + threadIdx.x;   // over PLANE/4
    size_t i4 = 4 * t;
    float v[3][4];
    #pragma unroll
    for (int g = 0; g < 3; ++g) {
        uint2 pa = *reinterpret_cast<const uint2*>(g_qa  + (size_t)g * PLANE + i4);
        uint2 pq = *reinterpret_cast<const uint2*>(g_q0h + (size_t)g * PLANE + i4);
        __half2 a0 = *reinterpret_cast<__half2*>(&pa.x);
        __half2 a1 = *reinterpret_cast<__half2*>(&pa.y);
        __half2 q0 = *reinterpret_cast<__half2*>(&pq.x);
        __half2 q1 = *reinterpret_cast<__half2*>(&pq.y);
        float2 fa0 = __half22float2(a0), fa1 = __half22float2(a1);
        float2 fq0 = __half22float2(q0), fq1 = __half22float2(q1);
        v[g][0] = fmaxf(fa0.x + fq0.x, 0.0f);
        v[g][1] = fmaxf(fa0.y + fq0.y, 0.0f);
        v[g][2] = fmaxf(fa1.x + fq1.x, 0.0f);
        v[g][3] = fmaxf(fa1.y + fq1.y, 0.0f);
    }
    float4* po = reinterpret_cast<float4*>(out + i4 * 3);
    po[0] = make_float4(v[0][0], v[1][0], v[2][0], v[0][1]);
    po[1] = make_float4(v[1][1], v[2][1], v[0][2], v[1][2]);
    po[2] = make_float4(v[2][2], v[0][3], v[1][3], v[2][3]);
}

// ---------------- launch ---------------------------------------------------
extern "C" void kernel_launch(void* const* d_in, const int* in_sizes, int n_in,
                              void* d_out, int out_size) {
    const float* x  = (const float*)d_in[0];
    const float* q  = (const float*)d_in[1];
    const float* W1 = (const float*)d_in[2];
    const float* b1 = (const float*)d_in[3];
    const float* W2 = (const float*)d_in[4];
    const float* b2 = (const float*)d_in[5];
    const float* W3 = (const float*)d_in[6];
    const float* b3 = (const float*)d_in[7];
    float* out = (float*)d_out;

    cudaFuncSetAttribute(layer_kernel,
                         cudaFuncAttributeMaxDynamicSharedMemorySize, SMEM_TOTAL);

    prep_xq_kernel<<<NROWS / 2, 256>>>(x, q);
    prep_w_kernel<<<2304, 256>>>(W1, W2, W3);

    dim3 grid(2, 512, 3);
    layer_kernel<<<grid, 256, SMEM_TOTAL>>>(0, 1, b1, 0);  // q0h -> qa, relu
    layer_kernel<<<grid, 256, SMEM_TOTAL>>>(1, 2, b2, 1);  // qa  -> qb, relu
    layer_kernel<<<grid, 256, SMEM_TOTAL>>>(2, 1, b3, 2);  // qb  -> qa, no relu

    finalize_kernel<<<NROWS / 4, 256>>>(out);
}

// round 14
// speedup vs baseline: 1.0403x; 1.0403x over previous
#include <cuda_runtime.h>
#include <cuda_fp16.h>
#include <cstdint>
#include <cstddef>

#define NROWS 65536
#define PLANE ((size_t)NROWS * 256)

__device__ __align__(128) __half g_xh [6 * PLANE];
__device__ __align__(128) __half g_q0h[3 * PLANE];
__device__ __align__(128) __half g_qa [3 * PLANE];
__device__ __align__(128) __half g_qb [3 * PLANE];
__device__ __align__(128) __half g_wcat[3 * 256 * 768];

#define SWZ(x) ((x) ^ (((x) >> 3) & 0x70))

// SMEM: bias 1KB, 3 stages of (A 16KB + B 16KB)
#define OFF_BIAS 0
#define OFF_STG  1024
#define STG_SZ   32768
#define SMEM_TOTAL (1024 + 3 * STG_SZ)   // 99328

__device__ __forceinline__ uint32_t s2u(const void* p) {
    return (uint32_t)__cvta_generic_to_shared(p);
}

#define CPA(dst, src) \
    asm volatile("cp.async.cg.shared.global [%0], [%1], 16;" \
                 :: "r"(dst), "l"(src) : "memory")
#define CPC() asm volatile("cp.async.commit_group;" ::: "memory")
#define CPW1() asm volatile("cp.async.wait_group 1;" ::: "memory")

#define LDSM4(r, addr) \
    asm volatile("ldmatrix.sync.aligned.m8n8.x4.shared.b16 {%0,%1,%2,%3}, [%4];" \
                 : "=r"((r)[0]), "=r"((r)[1]), "=r"((r)[2]), "=r"((r)[3]) \
                 : "r"(addr))

#define MMA(cr, av, b0v, b1v) \
    asm volatile("mma.sync.aligned.m16n8k16.row.col.f32.f16.f16.f32 " \
                 "{%0,%1,%2,%3}, {%4,%5,%6,%7}, {%8,%9}, {%0,%1,%2,%3};" \
                 : "+f"((cr)[0]), "+f"((cr)[1]), "+f"((cr)[2]), "+f"((cr)[3]) \
                 : "r"((av)[0]), "r"((av)[1]), "r"((av)[2]), "r"((av)[3]), \
                   "r"(b0v), "r"(b1v))

// ---------------- prep kernels ---------------------------------------------
__global__ void prep_xq_kernel(const float* __restrict__ x,
                               const float* __restrict__ q) {
    size_t t = (size_t)blockIdx.x * 256 + threadIdx.x;   // over PLANE/2
    size_t i2 = 2 * t;
    const float4* px = reinterpret_cast<const float4*>(x + i2 * 6);
    float4 r0 = px[0], r1 = px[1], r2 = px[2];
    __half2* xh2 = reinterpret_cast<__half2*>(g_xh);
    xh2[0 * (PLANE / 2) + t] = __floats2half2_rn(r0.x, r1.z);
    xh2[1 * (PLANE / 2) + t] = __floats2half2_rn(r0.y, r1.w);
    xh2[2 * (PLANE / 2) + t] = __floats2half2_rn(r0.z, r2.x);
    xh2[3 * (PLANE / 2) + t] = __floats2half2_rn(r0.w, r2.y);
    xh2[4 * (PLANE / 2) + t] = __floats2half2_rn(r1.x, r2.z);
    xh2[5 * (PLANE / 2) + t] = __floats2half2_rn(r1.y, r2.w);

    const float2* pq = reinterpret_cast<const float2*>(q + i2 * 3);
    float2 s0 = pq[0], s1 = pq[1], s2 = pq[2];
    __half2* qh2 = reinterpret_cast<__half2*>(g_q0h);
    qh2[0 * (PLANE / 2) + t] = __floats2half2_rn(s0.x, s1.y);
    qh2[1 * (PLANE / 2) + t] = __floats2half2_rn(s0.y, s2.x);
    qh2[2 * (PLANE / 2) + t] = __floats2half2_rn(s1.x, s2.y);
}
__global__ void prep_w_kernel(const float* __restrict__ W1,
                              const float* __restrict__ W2,
                              const float* __restrict__ W3) {
    uint32_t t = blockIdx.x * 256 + threadIdx.x;   // 3*256*768
    int l = t / 196608, r = t % 196608;
    int o = r / 768, k = r % 768;
    int j = k >> 8, c = k & 255;
    const float* W = (l == 0) ? W1 : (l == 1 ? W2 : W3);
    g_wcat[t] = __float2half(W[(o * 256 + c) * 3 + j]);
}

// ---------------- layer kernel ---------------------------------------------
// grid: (2 n-halves, 512 row-tiles, 3 groups), 256 threads
__global__ void __launch_bounds__(256, 2)
layer_kernel(int qin_sel, int qout_sel, const float* __restrict__ bias, int layer) {
    extern __shared__ char smem[];
    const int tid   = threadIdx.x;
    const int lane  = tid & 31;
    const int wid   = tid >> 5;
    const int warpM = wid & 3;       // 4 warps in M (32 rows each)
    const int warpN = wid >> 2;      // 2 warps in N (64 cols each)
    const int half  = blockIdx.x;
    const int row0  = blockIdx.y * 128;
    const int g     = blockIdx.z;
    const int ncta  = half * 128;

    const __half* __restrict__ qin =
        (qin_sel == 0) ? g_q0h : (qin_sel == 1 ? g_qa : g_qb);
    __half* __restrict__ qout = (qout_sel == 1) ? g_qa : g_qb;
    const __half* __restrict__ wc = g_wcat + (size_t)layer * (256 * 768);

    const __half* aplane[3];
    aplane[0] = g_xh + (size_t)(2 * g + 0) * PLANE + (size_t)row0 * 256;
    aplane[1] = g_xh + (size_t)(2 * g + 1) * PLANE + (size_t)row0 * 256;
    aplane[2] = qin  + (size_t)g * PLANE          + (size_t)row0 * 256;
    const __half* bsrc = wc + (size_t)ncta * 768;

    float* bias_s = reinterpret_cast<float*>(smem + OFF_BIAS);
    if (tid < 128) bias_s[tid] = bias[ncta + tid];

    const uint32_t sb = s2u(smem);
    const int ldm = tid >> 3, ldt = (tid & 7) * 8;

    // loadChunk writes to explicit stage base address
    auto loadChunk = [&](int c, uint32_t dA) {
        const __half* sA = aplane[c >> 2] + (c & 3) * 64;
        #pragma unroll
        for (int it = 0; it < 4; ++it) {           // A: 128 rows x 128B
            int m = ldm + it * 32;
            CPA(dA + SWZ(m * 128 + ldt * 2), sA + (size_t)m * 256 + ldt);
        }
        const __half* sB = bsrc + c * 64;
        const uint32_t dB = dA + 16384;
        #pragma unroll
        for (int it = 0; it < 4; ++it) {           // B: 128 n-rows x 128B
            int n = ldm + it * 32;
            CPA(dB + SWZ(n * 128 + ldt * 2), sB + (size_t)n * 768 + ldt);
        }
    };

    float c[2][8][4];
    #pragma unroll
    for (int mt = 0; mt < 2; ++mt)
        #pragma unroll
        for (int j = 0; j < 8; ++j)
            #pragma unroll
            for (int e = 0; e < 4; ++e) c[mt][j][e] = 0.0f;

    const int arow = warpM * 32 + (lane & 15);
    const int akb  = (lane >> 4) * 8;
    const int brow = warpN * 64 + ((lane >> 3) & 2) * 4 + (lane & 7);
    const int bkb  = ((lane >> 3) & 1) * 8;

    uint32_t a[2][2][4], b[2][4][4];

    const uint32_t stgBase = sb + OFF_STG;
    const uint32_t stgTop  = sb + OFF_STG + 2 * STG_SZ;

    loadChunk(0, stgBase);             CPC();
    loadChunk(1, stgBase + STG_SZ);    CPC();

    uint32_t aoff = stgBase;           // stage holding chunk i
    uint32_t loff = stgTop;            // stage receiving chunk i+2

    #pragma unroll 1
    for (int i = 0; i < 12; ++i) {
        CPW1();
        __syncthreads();
        if (i + 2 < 12) loadChunk(i + 2, loff);
        CPC();

        const uint32_t boff = aoff + 16384;

        // prime ks=0 frags
        #pragma unroll
        for (int mt = 0; mt < 2; ++mt)
            LDSM4(a[0][mt], aoff + SWZ((arow + mt * 16) * 128 + akb * 2));
        #pragma unroll
        for (int j = 0; j < 4; ++j)
            LDSM4(b[0][j], boff + SWZ((brow + j * 16) * 128 + bkb * 2));

        #pragma unroll
        for (int ks = 0; ks < 4; ++ks) {
            const int cur = ks & 1, nxt = cur ^ 1;
            if (ks < 3) {
                const int k0 = (ks + 1) * 16;
                #pragma unroll
                for (int mt = 0; mt < 2; ++mt)
                    LDSM4(a[nxt][mt], aoff + SWZ((arow + mt * 16) * 128 + (k0 + akb) * 2));
                #pragma unroll
                for (int j = 0; j < 4; ++j)
                    LDSM4(b[nxt][j], boff + SWZ((brow + j * 16) * 128 + (k0 + bkb) * 2));
            }
            #pragma unroll
            for (int mt = 0; mt < 2; ++mt)
                #pragma unroll
                for (int j = 0; j < 4; ++j) {
                    MMA(c[mt][2 * j],     a[cur][mt], b[cur][j][0], b[cur][j][1]);
                    MMA(c[mt][2 * j + 1], a[cur][mt], b[cur][j][2], b[cur][j][3]);
                }
        }

        // rotate stage offsets (replaces i%3 indexing)
        aoff = (aoff == stgTop) ? stgBase : aoff + STG_SZ;
        loff = (loff == stgTop) ? stgBase : loff + STG_SZ;
    }

    // epilogue: bias + relu -> fp16 planar (final layer relu lives in finalize)
    __half* plane = qout + (size_t)g * PLANE;
    const int do_relu = (layer != 2);
    #pragma unroll
    for (int mt = 0; mt < 2; ++mt) {
        const int r0 = row0 + warpM * 32 + mt * 16 + (lane >> 2);
        #pragma unroll
        for (int j = 0; j < 8; ++j) {
            const int cl = warpN * 64 + j * 8 + (lane & 3) * 2;
            const float b0 = bias_s[cl], b1 = bias_s[cl + 1];
            float v0 = c[mt][j][0] + b0, v1 = c[mt][j][1] + b1;
            float v2 = c[mt][j][2] + b0, v3 = c[mt][j][3] + b1;
            if (do_relu) {
                v0 = fmaxf(v0, 0.0f); v1 = fmaxf(v1, 0.0f);
                v2 = fmaxf(v2, 0.0f); v3 = fmaxf(v3, 0.0f);
            }
            const int gc = ncta + cl;
            *reinterpret_cast<__half2*>(plane + (size_t)r0 * 256 + gc) =
                __floats2half2_rn(v0, v1);
            *reinterpret_cast<__half2*>(plane + (size_t)(r0 + 8) * 256 + gc) =
                __floats2half2_rn(v2, v3);
        }
    }
}

// ---------------- finalize: residual(fp16) + relu + interleave -------------
__global__ void finalize_kernel(float* __restrict__ out) {
    size_t t = (size_t)blockIdx.x * 256 + threadIdx.x;   // over PLANE/4
    size_t i4 = 4 * t;
    float v[3][4];
    #pragma unroll
    for (int g = 0; g < 3; ++g) {
        uint2 pa = *reinterpret_cast<const uint2*>(g_qa  + (size_t)g * PLANE + i4);
        uint2 pq = *reinterpret_cast<const uint2*>(g_q0h + (size_t)g * PLANE + i4);
        __half2 a0 = *reinterpret_cast<__half2*>(&pa.x);
        __half2 a1 = *reinterpret_cast<__half2*>(&pa.y);
        __half2 q0 = *reinterpret_cast<__half2*>(&pq.x);
        __half2 q1 = *reinterpret_cast<__half2*>(&pq.y);
        float2 fa0 = __half22float2(a0), fa1 = __half22float2(a1);
        float2 fq0 = __half22float2(q0), fq1 = __half22float2(q1);
        v[g][0] = fmaxf(fa0.x + fq0.x, 0.0f);
        v[g][1] = fmaxf(fa0.y + fq0.y, 0.0f);
        v[g][2] = fmaxf(fa1.x + fq1.x, 0.0f);
        v[g][3] = fmaxf(fa1.y + fq1.y, 0.0f);
    }
    float4* po = reinterpret_cast<float4*>(out + i4 * 3);
    po[0] = make_float4(v[0][0], v[1][0], v[2][0], v[0][1]);
    po[1] = make_float4(v[1][1], v[2][1], v[0][2], v[1][2]);
    po[2] = make_float4(v[2][2], v[0][3], v[1][3], v[2][3]);
}

// ---------------- launch ---------------------------------------------------
extern "C" void kernel_launch(void* const* d_in, const int* in_sizes, int n_in,
                              void* d_out, int out_size) {
    const float* x  = (const float*)d_in[0];
    const float* q  = (const float*)d_in[1];
    const float* W1 = (const float*)d_in[2];
    const float* b1 = (const float*)d_in[3];
    const float* W2 = (const float*)d_in[4];
    const float* b2 = (const float*)d_in[5];
    const float* W3 = (const float*)d_in[6];
    const float* b3 = (const float*)d_in[7];
    float* out = (float*)d_out;

    cudaFuncSetAttribute(layer_kernel,
                         cudaFuncAttributeMaxDynamicSharedMemorySize, SMEM_TOTAL);

    prep_xq_kernel<<<NROWS / 2, 256>>>(x, q);
    prep_w_kernel<<<2304, 256>>>(W1, W2, W3);

    dim3 grid(2, 512, 3);
    layer_kernel<<<grid, 256, SMEM_TOTAL>>>(0, 1, b1, 0);  // q0h -> qa, relu
    layer_kernel<<<grid, 256, SMEM_TOTAL>>>(1, 2, b2, 1);  // qa  -> qb, relu
    layer_kernel<<<grid, 256, SMEM_TOTAL>>>(2, 1, b3, 2);  // qb  -> qa, no relu

    finalize_kernel<<<NROWS / 4, 256>>>(out);
}